// round 15
// baseline (speedup 1.0000x reference)
#include <cuda_runtime.h>
#include <cuda_bf16.h>
#include <cstdint>
#include <math.h>

// Problem constants
#define BATCH 2
#define SEQ   2048
#define HID   1024
#define NH    16
#define HD    64
#define MROWS (BATCH * SEQ)   // 4096

static const size_t OUT_ELEMS  = (size_t)BATCH * SEQ * HID;              // 4,194,304
static const size_t ATTN_ELEMS = (size_t)BATCH * NH * SEQ * (size_t)SEQ; // 134,217,728

// Scratch (allocation-free: __device__ globals)
__device__ __align__(16) float g_attn_scratch[(size_t)BATCH * NH * SEQ * (size_t)SEQ];

// bf16 hi/lo splits
__device__ __align__(16) __nv_bfloat16 g_ah[MROWS * HID];   // x hi
__device__ __align__(16) __nv_bfloat16 g_al[MROWS * HID];   // x lo
__device__ __align__(16) __nv_bfloat16 g_wh[4 * HID * HID]; // weights hi (q,k,v,o)
__device__ __align__(16) __nv_bfloat16 g_wl[4 * HID * HID]; // weights lo
__device__ __align__(16) __nv_bfloat16 g_qh[MROWS * HID];
__device__ __align__(16) __nv_bfloat16 g_ql[MROWS * HID];
__device__ __align__(16) __nv_bfloat16 g_kh[MROWS * HID];
__device__ __align__(16) __nv_bfloat16 g_kl[MROWS * HID];
__device__ __align__(16) __nv_bfloat16 g_vh[MROWS * HID];
__device__ __align__(16) __nv_bfloat16 g_vl[MROWS * HID];
__device__ __align__(16) __nv_bfloat16 g_cth[MROWS * HID];  // ctx hi
__device__ __align__(16) __nv_bfloat16 g_ctl[MROWS * HID];  // ctx lo

// ---------------------------------------------------------------------------
// PTX helpers (sm_80-baseline features only)
// ---------------------------------------------------------------------------
__device__ __forceinline__ uint32_t smem_u32(const void* p) {
    uint32_t a;
    asm("{ .reg .u64 t; cvta.to.shared.u64 t, %1; cvt.u32.u64 %0, t; }" : "=r"(a) : "l"(p));
    return a;
}

#define CP_ASYNC16(dst, src) \
    asm volatile("cp.async.cg.shared.global [%0], [%1], 16;" :: "r"(dst), "l"(src) : "memory")
#define CP_COMMIT() asm volatile("cp.async.commit_group;" ::: "memory")
#define CP_WAIT(N)  asm volatile("cp.async.wait_group %0;" :: "n"(N) : "memory")

#define LDM4(r, a)                                                              \
    asm volatile("ldmatrix.sync.aligned.m8n8.x4.shared.b16 {%0,%1,%2,%3}, [%4];" \
                 : "=r"((r)[0]), "=r"((r)[1]), "=r"((r)[2]), "=r"((r)[3]) : "r"(a))

#define LDM4T(r, a)                                                                   \
    asm volatile("ldmatrix.sync.aligned.m8n8.x4.trans.shared.b16 {%0,%1,%2,%3}, [%4];" \
                 : "=r"((r)[0]), "=r"((r)[1]), "=r"((r)[2]), "=r"((r)[3]) : "r"(a))

#define MMA16816(c, a, b0, b1)                                                  \
    asm volatile("mma.sync.aligned.m16n8k16.row.col.f32.bf16.bf16.f32 "         \
                 "{%0,%1,%2,%3}, {%4,%5,%6,%7}, {%8,%9}, {%0,%1,%2,%3};"        \
                 : "+f"((c)[0]), "+f"((c)[1]), "+f"((c)[2]), "+f"((c)[3])       \
                 : "r"((a)[0]), "r"((a)[1]), "r"((a)[2]), "r"((a)[3]),          \
                   "r"(b0), "r"(b1))

// streaming stores — write-once data, keep it out of L2's working set
#define STG_CS_F2(addr, x, y) \
    asm volatile("st.global.cs.v2.f32 [%0], {%1, %2};" :: "l"(addr), "f"(x), "f"(y) : "memory")
#define STG_CS_F4Z(addr) \
    asm volatile("st.global.cs.v4.f32 [%0], {%1, %1, %1, %1};" :: "l"(addr), "f"(0.f) : "memory")

__device__ __forceinline__ float ex2f(float x) {
    float r; asm("ex2.approx.f32 %0, %1;" : "=f"(r) : "f"(x)); return r;
}
__device__ __forceinline__ void split2(float x, float y, uint32_t& hi, uint32_t& lo) {
    __nv_bfloat16 hx = __float2bfloat16(x), hy = __float2bfloat16(y);
    __nv_bfloat162 hp(hx, hy);
    hi = *(uint32_t*)&hp;
    __nv_bfloat162 lp = __floats2bfloat162_rn(x - __bfloat162float(hx),
                                              y - __bfloat162float(hy));
    lo = *(uint32_t*)&lp;
}

// ---------------------------------------------------------------------------
// fp32 -> bf16 hi/lo split (x and weights only — everything else is fused)
// ---------------------------------------------------------------------------
__global__ __launch_bounds__(256) void conv_split(
    const float* __restrict__ src, __nv_bfloat16* __restrict__ hi,
    __nv_bfloat16* __restrict__ lo, int n)
{
    int i = (blockIdx.x * 256 + threadIdx.x) * 4;
    if (i >= n) return;
    float4 v = *(const float4*)&src[i];
    __nv_bfloat16 h0 = __float2bfloat16(v.x), h1 = __float2bfloat16(v.y);
    __nv_bfloat16 h2 = __float2bfloat16(v.z), h3 = __float2bfloat16(v.w);
    __nv_bfloat16 l0 = __float2bfloat16(v.x - __bfloat162float(h0));
    __nv_bfloat16 l1 = __float2bfloat16(v.y - __bfloat162float(h1));
    __nv_bfloat16 l2 = __float2bfloat16(v.z - __bfloat162float(h2));
    __nv_bfloat16 l3 = __float2bfloat16(v.w - __bfloat162float(h3));
    *(__nv_bfloat162*)&hi[i]     = __nv_bfloat162(h0, h1);
    *(__nv_bfloat162*)&hi[i + 2] = __nv_bfloat162(h2, h3);
    *(__nv_bfloat162*)&lo[i]     = __nv_bfloat162(l0, l1);
    *(__nv_bfloat162*)&lo[i + 2] = __nv_bfloat162(l2, l3);
}

// ---------------------------------------------------------------------------
// Tensor-core (mma.sync bf16) 3-split GEMM:
//   acc = Ah@Bh^T + Ah@Bl^T + Al@Bh^T + bias
// EMODE 0: write fp32 C.  EMODE 1: write bf16 hi/lo pair (fused conv_split).
// ---------------------------------------------------------------------------
#define GM_STEPS (HID / 32)
#define GM_TPAD  80
#define GM_TILE  (128 * GM_TPAD)
#define GM_BUF   (4 * GM_TILE)
#define GM_SMEM  (2 * GM_BUF)

template <int EMODE>
__global__ __launch_bounds__(256, 2) void gemm_mma(
    const __nv_bfloat16* __restrict__ Ah, const __nv_bfloat16* __restrict__ Al,
    const __nv_bfloat16* __restrict__ Bh, const __nv_bfloat16* __restrict__ Bl,
    const float* __restrict__ bias, float* __restrict__ Cf,
    __nv_bfloat16* __restrict__ Ch, __nv_bfloat16* __restrict__ Cl,
    int M, int N)
{
    extern __shared__ __align__(128) char sm[];
    const uint32_t smb = smem_u32(sm);
    const int tid = threadIdx.x;
    const int lane = tid & 31, w = tid >> 5;
    const int wr = w >> 2;
    const int wc = w & 3;
    const int m0 = blockIdx.y * 128, n0 = blockIdx.x * 128;
    const int K = HID;

    const __nv_bfloat16* gb[4] = {
        Ah + (size_t)m0 * K, Al + (size_t)m0 * K,
        Bh + (size_t)n0 * K, Bl + (size_t)n0 * K };

    auto load_step = [&](int b, int k0) {
        uint32_t bufb = smb + b * GM_BUF;
        #pragma unroll
        for (int j = 0; j < 8; j++) {
            int i = tid + j * 256;
            int t = i >> 9;
            int r = (i >> 2) & 127;
            int c = i & 3;
            const __nv_bfloat16* src = gb[t] + (size_t)r * K + k0 + c * 8;
            uint32_t dst = bufb + t * GM_TILE + r * GM_TPAD + c * 16;
            CP_ASYNC16(dst, src);
        }
    };

    float acc[4][4][4];
    #pragma unroll
    for (int mi = 0; mi < 4; mi++)
        #pragma unroll
        for (int nt = 0; nt < 4; nt++)
            #pragma unroll
            for (int r = 0; r < 4; r++) acc[mi][nt][r] = 0.f;

    const uint32_t a_off = (uint32_t)(wr * 64 + (lane & 15)) * GM_TPAD + (lane >> 4) * 16;
    const int q = lane >> 3;
    const uint32_t b_off = (uint32_t)(wc * 32 + (q >> 1) * 8 + (lane & 7)) * GM_TPAD
                         + (q & 1) * 16;

    load_step(0, 0);
    CP_COMMIT();

    for (int t = 0; t < GM_STEPS; t++) {
        if (t + 1 < GM_STEPS) {
            load_step((t + 1) & 1, (t + 1) * 32);
            CP_COMMIT();
            CP_WAIT(1);
        } else {
            CP_WAIT(0);
        }
        __syncthreads();

        const uint32_t bb = smb + (t & 1) * GM_BUF;
        #pragma unroll
        for (int kk = 0; kk < 2; kk++) {
            const uint32_t kb = kk * 32;
            uint32_t af[4][4], bh[4][2], bl[4][2];

            #pragma unroll
            for (int p = 0; p < 2; p++) {
                uint32_t rb = bb + 2 * GM_TILE + b_off + p * 16 * GM_TPAD + kb;
                uint32_t tmp[4];
                LDM4(tmp, rb);
                bh[2 * p][0] = tmp[0]; bh[2 * p][1] = tmp[1];
                bh[2 * p + 1][0] = tmp[2]; bh[2 * p + 1][1] = tmp[3];
                LDM4(tmp, rb + GM_TILE);
                bl[2 * p][0] = tmp[0]; bl[2 * p][1] = tmp[1];
                bl[2 * p + 1][0] = tmp[2]; bl[2 * p + 1][1] = tmp[3];
            }

            #pragma unroll
            for (int mi = 0; mi < 4; mi++) {
                LDM4(af[mi], bb + a_off + (uint32_t)mi * 16 * GM_TPAD + kb);
            }
            #pragma unroll
            for (int mi = 0; mi < 4; mi++)
                #pragma unroll
                for (int nt = 0; nt < 4; nt++) {
                    MMA16816(acc[mi][nt], af[mi], bh[nt][0], bh[nt][1]);
                    MMA16816(acc[mi][nt], af[mi], bl[nt][0], bl[nt][1]);
                }

            #pragma unroll
            for (int mi = 0; mi < 4; mi++) {
                LDM4(af[mi], bb + GM_TILE + a_off + (uint32_t)mi * 16 * GM_TPAD + kb);
            }
            #pragma unroll
            for (int mi = 0; mi < 4; mi++)
                #pragma unroll
                for (int nt = 0; nt < 4; nt++)
                    MMA16816(acc[mi][nt], af[mi], bh[nt][0], bh[nt][1]);
        }
        __syncthreads();
    }

    const int rbase = m0 + wr * 64 + (lane >> 2);
    #pragma unroll
    for (int nt = 0; nt < 4; nt++) {
        const int col = n0 + wc * 32 + nt * 8 + (lane & 3) * 2;
        const float2 bv = *(const float2*)&bias[col];
        #pragma unroll
        for (int mi = 0; mi < 4; mi++) {
            int r0 = rbase + mi * 16;
            float v00 = acc[mi][nt][0] + bv.x, v01 = acc[mi][nt][1] + bv.y;
            float v10 = acc[mi][nt][2] + bv.x, v11 = acc[mi][nt][3] + bv.y;
            if (EMODE == 0) {
                *(float2*)&Cf[(size_t)r0 * N + col]       = make_float2(v00, v01);
                *(float2*)&Cf[(size_t)(r0 + 8) * N + col] = make_float2(v10, v11);
            } else {
                uint32_t hi, lo;
                split2(v00, v01, hi, lo);
                *(uint32_t*)&Ch[(size_t)r0 * N + col] = hi;
                *(uint32_t*)&Cl[(size_t)r0 * N + col] = lo;
                split2(v10, v11, hi, lo);
                *(uint32_t*)&Ch[(size_t)(r0 + 8) * N + col] = hi;
                *(uint32_t*)&Cl[(size_t)(r0 + 8) * N + col] = lo;
            }
        }
    }
}

// ---------------------------------------------------------------------------
// Tensor-core causal flash attention (mma.sync, bf16 3-split).
// CTA: 256 threads = 8 warps; Q row tile 128 (warp = 16 rows); j-tile 64.
// 2 CTAs/SM (smem 110592*2 = 216 KB fits; regs capped at 128 by bounds).
// Phase 1: S = QK^T (3-term), online (m, l) stats only.
// Phase 2: recompute S, p = exp2(s*C - m)/l, write P (.cs), ctx += P@V.
// ctx emitted directly as bf16 hi/lo for the O-projection.
// ---------------------------------------------------------------------------
#define AT_STRIDE 144
#define AT_QTILE  (128 * AT_STRIDE)
#define AT_Q      (2 * AT_QTILE)
#define AT_KVT    (64 * AT_STRIDE)
#define AT_KVBUF  (4 * AT_KVT)
#define AT_SMEM   (AT_Q + 2 * AT_KVBUF)
#define C_SCALE   11.5415603270f         // 8 * log2(e)

__global__ __launch_bounds__(256, 2) void attn_mma(
    const __nv_bfloat16* __restrict__ qh, const __nv_bfloat16* __restrict__ ql,
    const __nv_bfloat16* __restrict__ kh, const __nv_bfloat16* __restrict__ kl,
    const __nv_bfloat16* __restrict__ vh, const __nv_bfloat16* __restrict__ vl,
    float* __restrict__ attn,
    __nv_bfloat16* __restrict__ cth, __nv_bfloat16* __restrict__ ctl)
{
    extern __shared__ __align__(1024) char smc[];
    const uint32_t smb = smem_u32(smc);
    const int tid = threadIdx.x, lane = tid & 31, w = tid >> 5;
    const int mt = (int)gridDim.x - 1 - (int)blockIdx.x;   // heavy-first
    const int bh = blockIdx.y, b = bh >> 4, h = bh & 15;
    const int m0 = mt * 128;
    const int njt = 2 * mt + 2;
    const size_t hoff = (size_t)b * SEQ * HID + h * 64;
    const __nv_bfloat16* src[6] = { qh + hoff, ql + hoff, kh + hoff,
                                    kl + hoff, vh + hoff, vl + hoff };
    float* arow = attn + (size_t)bh * SEQ * SEQ;

    for (int i = tid; i < 2048; i += 256) {
        int t = i >> 10, r = (i >> 3) & 127, c = i & 7;
        CP_ASYNC16(smb + t * AT_QTILE + r * AT_STRIDE + c * 16,
                   src[t] + (size_t)(m0 + r) * HID + c * 8);
    }
    CP_COMMIT();

    auto load_kv = [&](int buf, int jt, int ntiles) {
        uint32_t base = smb + AT_Q + buf * AT_KVBUF;
        int j0 = jt * 64;
        for (int i = tid; i < ntiles * 512; i += 256) {
            int t = i >> 9, r = (i >> 3) & 63, c = i & 7;
            CP_ASYNC16(base + t * AT_KVT + r * AT_STRIDE + c * 16,
                       src[2 + t] + (size_t)(j0 + r) * HID + c * 8);
        }
    };

    const int wq = w * 16;
    const uint32_t qa  = smb + (uint32_t)(wq + (lane & 15)) * AT_STRIDE + (lane >> 4) * 16;
    const int q2 = lane >> 3;
    const uint32_t kfo = (uint32_t)((q2 >> 1) * 8 + (lane & 7)) * AT_STRIDE + (q2 & 1) * 16;
    const int rbase = m0 + wq + (lane >> 2);

    uint32_t qhf[4][4];
    bool qloaded = false;

    auto compute_S = [&](uint32_t kb, float (*sacc)[4]) {
        #pragma unroll
        for (int nt = 0; nt < 8; nt++)
            #pragma unroll
            for (int r = 0; r < 4; r++) sacc[nt][r] = 0.f;
        #pragma unroll
        for (int kt = 0; kt < 4; kt++) {
            uint32_t qlf[4];
            LDM4(qlf, qa + AT_QTILE + kt * 32);
            #pragma unroll
            for (int p = 0; p < 4; p++) {
                uint32_t kh4[4], kl4[4];
                uint32_t ka = kb + kfo + (uint32_t)p * 16 * AT_STRIDE + kt * 32;
                LDM4(kh4, ka);
                LDM4(kl4, ka + AT_KVT);
                MMA16816(sacc[2 * p],     qhf[kt], kh4[0], kh4[1]);
                MMA16816(sacc[2 * p + 1], qhf[kt], kh4[2], kh4[3]);
                MMA16816(sacc[2 * p],     qhf[kt], kl4[0], kl4[1]);
                MMA16816(sacc[2 * p + 1], qhf[kt], kl4[2], kl4[3]);
                MMA16816(sacc[2 * p],     qlf, kh4[0], kh4[1]);
                MMA16816(sacc[2 * p + 1], qlf, kh4[2], kh4[3]);
            }
        }
    };

    float m_[2] = { -1e30f, -1e30f };
    float l_[2] = { 0.f, 0.f };

    // ---------------- phase 1: stats ----------------
    load_kv(0, 0, 2);
    CP_COMMIT();
    for (int jt = 0; jt < njt; jt++) {
        if (jt + 1 < njt) { load_kv((jt + 1) & 1, jt + 1, 2); CP_COMMIT(); CP_WAIT(1); }
        else              { CP_WAIT(0); }
        __syncthreads();
        if (!qloaded) {
            qloaded = true;
            #pragma unroll
            for (int kt = 0; kt < 4; kt++) LDM4(qhf[kt], qa + kt * 32);
        }

        const uint32_t kb = smb + AT_Q + (jt & 1) * AT_KVBUF;
        float sacc[8][4];
        compute_S(kb, sacc);

        const int colb = jt * 64 + (lane & 3) * 2;
        #pragma unroll
        for (int hf = 0; hf < 2; hf++) {
            const int row = rbase + 8 * hf;
            float sv[16];
            float tmax = -1e30f;
            #pragma unroll
            for (int nt = 0; nt < 8; nt++) {
                int c0 = colb + nt * 8;
                float s0 = (c0     > row) ? -1e30f : sacc[nt][2 * hf]     * C_SCALE;
                float s1 = (c0 + 1 > row) ? -1e30f : sacc[nt][2 * hf + 1] * C_SCALE;
                sv[2 * nt] = s0; sv[2 * nt + 1] = s1;
                tmax = fmaxf(tmax, fmaxf(s0, s1));
            }
            tmax = fmaxf(tmax, __shfl_xor_sync(0xffffffffu, tmax, 1));
            tmax = fmaxf(tmax, __shfl_xor_sync(0xffffffffu, tmax, 2));
            float mnew = fmaxf(m_[hf], tmax);
            float s = 0.f;
            #pragma unroll
            for (int e = 0; e < 16; e++) s += ex2f(sv[e] - mnew);
            s += __shfl_xor_sync(0xffffffffu, s, 1);
            s += __shfl_xor_sync(0xffffffffu, s, 2);
            l_[hf] = l_[hf] * ex2f(m_[hf] - mnew) + s;
            m_[hf] = mnew;
        }
        __syncthreads();
    }

    const float invl[2] = { 1.f / l_[0], 1.f / l_[1] };

    // ---------------- phase 2: P + PV ----------------
    float cacc[8][4];
    #pragma unroll
    for (int nt = 0; nt < 8; nt++)
        #pragma unroll
        for (int r = 0; r < 4; r++) cacc[nt][r] = 0.f;

    load_kv(0, 0, 4);
    CP_COMMIT();
    for (int jt = 0; jt < njt; jt++) {
        if (jt + 1 < njt) { load_kv((jt + 1) & 1, jt + 1, 4); CP_COMMIT(); CP_WAIT(1); }
        else              { CP_WAIT(0); }
        __syncthreads();

        const uint32_t kb = smb + AT_Q + (jt & 1) * AT_KVBUF;
        float sacc[8][4];
        compute_S(kb, sacc);

        const int colb = jt * 64 + (lane & 3) * 2;
        uint32_t aph[4][4], apl[4][4];
        #pragma unroll
        for (int nt = 0; nt < 8; nt++) {
            int c0 = colb + nt * 8;
            int kj = nt >> 1, sub = nt & 1;
            #pragma unroll
            for (int hf = 0; hf < 2; hf++) {
                const int row = rbase + 8 * hf;
                float p0 = (c0     > row) ? 0.f
                         : ex2f(fmaf(sacc[nt][2 * hf],     C_SCALE, -m_[hf])) * invl[hf];
                float p1 = (c0 + 1 > row) ? 0.f
                         : ex2f(fmaf(sacc[nt][2 * hf + 1], C_SCALE, -m_[hf])) * invl[hf];
                STG_CS_F2(&arow[(size_t)row * SEQ + c0], p0, p1);
                split2(p0, p1, aph[kj][sub * 2 + hf], apl[kj][sub * 2 + hf]);
            }
        }

        const uint32_t vb = kb + 2 * AT_KVT;
        const uint32_t vfo = vb + (uint32_t)(lane & 15) * AT_STRIDE + (lane >> 4) * 16;
        #pragma unroll
        for (int kj = 0; kj < 4; kj++) {
            #pragma unroll
            for (int dp = 0; dp < 4; dp++) {
                uint32_t vh4[4], vl4[4];
                uint32_t va = vfo + (uint32_t)kj * 16 * AT_STRIDE + dp * 32;
                LDM4T(vh4, va);
                LDM4T(vl4, va + AT_KVT);
                MMA16816(cacc[2 * dp],     aph[kj], vh4[0], vh4[1]);
                MMA16816(cacc[2 * dp + 1], aph[kj], vh4[2], vh4[3]);
                MMA16816(cacc[2 * dp],     aph[kj], vl4[0], vl4[1]);
                MMA16816(cacc[2 * dp + 1], aph[kj], vl4[2], vl4[3]);
                MMA16816(cacc[2 * dp],     apl[kj], vh4[0], vh4[1]);
                MMA16816(cacc[2 * dp + 1], apl[kj], vh4[2], vh4[3]);
            }
        }
        __syncthreads();
    }

    // ctx write — fused bf16 hi/lo split
    #pragma unroll
    for (int hf = 0; hf < 2; hf++) {
        const int row = rbase + 8 * hf;
        size_t off = ((size_t)b * SEQ + row) * HID + h * 64 + (lane & 3) * 2;
        #pragma unroll
        for (int nt = 0; nt < 8; nt++) {
            uint32_t hi, lo;
            split2(cacc[nt][2 * hf], cacc[nt][2 * hf + 1], hi, lo);
            *(uint32_t*)&cth[off + nt * 8] = hi;
            *(uint32_t*)&ctl[off + nt * 8] = lo;
        }
    }

    // zero-fill fully masked columns (streaming stores)
    const int zstart = m0 + 128;
    const int zc = SEQ - zstart;
    if (zc > 0) {
        const int nv = zc >> 2;
        for (int it = tid; it < 128 * nv; it += 256) {
            int r = it / nv, c = it - r * nv;
            STG_CS_F4Z(&arow[(size_t)(m0 + r) * SEQ + zstart + c * 4]);
        }
    }
}

// ---------------------------------------------------------------------------
extern "C" void kernel_launch(void* const* d_in, const int* in_sizes, int n_in,
                              void* d_out, int out_size)
{
    const float* x  = (const float*)d_in[0];
    const float* Wq = (const float*)d_in[1];
    const float* bq = (const float*)d_in[2];
    const float* Wk = (const float*)d_in[3];
    const float* bk = (const float*)d_in[4];
    const float* Wv = (const float*)d_in[5];
    const float* bv = (const float*)d_in[6];
    const float* Wo = (const float*)d_in[7];
    const float* bo = (const float*)d_in[8];

    float* out = (float*)d_out;

    void *pattn, *pah, *pal, *pwh, *pwl;
    void *pqh, *pql, *pkh, *pkl, *pvh, *pvl, *pcth, *pctl;
    cudaGetSymbolAddress(&pattn, g_attn_scratch);
    cudaGetSymbolAddress(&pah, g_ah);
    cudaGetSymbolAddress(&pal, g_al);
    cudaGetSymbolAddress(&pwh, g_wh);
    cudaGetSymbolAddress(&pwl, g_wl);
    cudaGetSymbolAddress(&pqh, g_qh);
    cudaGetSymbolAddress(&pql, g_ql);
    cudaGetSymbolAddress(&pkh, g_kh);
    cudaGetSymbolAddress(&pkl, g_kl);
    cudaGetSymbolAddress(&pvh, g_vh);
    cudaGetSymbolAddress(&pvl, g_vl);
    cudaGetSymbolAddress(&pcth, g_cth);
    cudaGetSymbolAddress(&pctl, g_ctl);

    __nv_bfloat16* ah = (__nv_bfloat16*)pah;
    __nv_bfloat16* al = (__nv_bfloat16*)pal;
    __nv_bfloat16* wh = (__nv_bfloat16*)pwh;
    __nv_bfloat16* wl = (__nv_bfloat16*)pwl;

    float* attn = ((size_t)out_size >= OUT_ELEMS + ATTN_ELEMS)
                      ? out + OUT_ELEMS
                      : (float*)pattn;

    cudaFuncSetAttribute(gemm_mma<0>, cudaFuncAttributeMaxDynamicSharedMemorySize, GM_SMEM);
    cudaFuncSetAttribute(gemm_mma<1>, cudaFuncAttributeMaxDynamicSharedMemorySize, GM_SMEM);
    cudaFuncSetAttribute(attn_mma, cudaFuncAttributeMaxDynamicSharedMemorySize, AT_SMEM);

    const int NW = HID * HID;    // 1,048,576
    const int NX = MROWS * HID;  // 4,194,304

    // input splits (x + 4 weights only)
    conv_split<<<NX / 1024, 256>>>(x, ah, al, NX);
    conv_split<<<NW / 1024, 256>>>(Wq, wh + 0 * (size_t)NW, wl + 0 * (size_t)NW, NW);
    conv_split<<<NW / 1024, 256>>>(Wk, wh + 1 * (size_t)NW, wl + 1 * (size_t)NW, NW);
    conv_split<<<NW / 1024, 256>>>(Wv, wh + 2 * (size_t)NW, wl + 2 * (size_t)NW, NW);
    conv_split<<<NW / 1024, 256>>>(Wo, wh + 3 * (size_t)NW, wl + 3 * (size_t)NW, NW);

    dim3 gG(HID / 128, MROWS / 128);  // (8, 32)
    // Q/K/V projections: bf16 hi/lo emitted directly (EMODE 1)
    gemm_mma<1><<<gG, 256, GM_SMEM>>>(ah, al, wh + 0 * (size_t)NW, wl + 0 * (size_t)NW,
                                      bq, nullptr,
                                      (__nv_bfloat16*)pqh, (__nv_bfloat16*)pql, MROWS, HID);
    gemm_mma<1><<<gG, 256, GM_SMEM>>>(ah, al, wh + 1 * (size_t)NW, wl + 1 * (size_t)NW,
                                      bk, nullptr,
                                      (__nv_bfloat16*)pkh, (__nv_bfloat16*)pkl, MROWS, HID);
    gemm_mma<1><<<gG, 256, GM_SMEM>>>(ah, al, wh + 2 * (size_t)NW, wl + 2 * (size_t)NW,
                                      bv, nullptr,
                                      (__nv_bfloat16*)pvh, (__nv_bfloat16*)pvl, MROWS, HID);

    dim3 gAttn(SEQ / 128, BATCH * NH);  // (16, 32)
    attn_mma<<<gAttn, 256, AT_SMEM>>>(
        (const __nv_bfloat16*)pqh, (const __nv_bfloat16*)pql,
        (const __nv_bfloat16*)pkh, (const __nv_bfloat16*)pkl,
        (const __nv_bfloat16*)pvh, (const __nv_bfloat16*)pvl,
        attn, (__nv_bfloat16*)pcth, (__nv_bfloat16*)pctl);

    // O projection consumes fused ctx hi/lo, writes fp32 out (EMODE 0)
    gemm_mma<0><<<gG, 256, GM_SMEM>>>((const __nv_bfloat16*)pcth, (const __nv_bfloat16*)pctl,
                                      wh + 3 * (size_t)NW, wl + 3 * (size_t)NW,
                                      bo, out, nullptr, nullptr, MROWS, HID);
}

// round 16
// speedup vs baseline: 1.0004x; 1.0004x over previous
#include <cuda_runtime.h>
#include <cuda_bf16.h>
#include <cstdint>
#include <math.h>

// Problem constants
#define BATCH 2
#define SEQ   2048
#define HID   1024
#define NH    16
#define HD    64
#define MROWS (BATCH * SEQ)   // 4096

static const size_t OUT_ELEMS  = (size_t)BATCH * SEQ * HID;              // 4,194,304
static const size_t ATTN_ELEMS = (size_t)BATCH * NH * SEQ * (size_t)SEQ; // 134,217,728

// Scratch (allocation-free: __device__ globals)
__device__ __align__(16) float g_attn_scratch[(size_t)BATCH * NH * SEQ * (size_t)SEQ];

// bf16 hi/lo splits
__device__ __align__(16) __nv_bfloat16 g_ah[MROWS * HID];   // x hi
__device__ __align__(16) __nv_bfloat16 g_al[MROWS * HID];   // x lo
__device__ __align__(16) __nv_bfloat16 g_wh[4 * HID * HID]; // weights hi (q,k,v,o)
__device__ __align__(16) __nv_bfloat16 g_wl[4 * HID * HID]; // weights lo
__device__ __align__(16) __nv_bfloat16 g_qh[MROWS * HID];
__device__ __align__(16) __nv_bfloat16 g_ql[MROWS * HID];
__device__ __align__(16) __nv_bfloat16 g_kh[MROWS * HID];
__device__ __align__(16) __nv_bfloat16 g_kl[MROWS * HID];
__device__ __align__(16) __nv_bfloat16 g_vh[MROWS * HID];
__device__ __align__(16) __nv_bfloat16 g_vl[MROWS * HID];
__device__ __align__(16) __nv_bfloat16 g_cth[MROWS * HID];  // ctx hi
__device__ __align__(16) __nv_bfloat16 g_ctl[MROWS * HID];  // ctx lo

// ---------------------------------------------------------------------------
// PTX helpers (sm_80-baseline features only)
// ---------------------------------------------------------------------------
__device__ __forceinline__ uint32_t smem_u32(const void* p) {
    uint32_t a;
    asm("{ .reg .u64 t; cvta.to.shared.u64 t, %1; cvt.u32.u64 %0, t; }" : "=r"(a) : "l"(p));
    return a;
}

#define CP_ASYNC16(dst, src) \
    asm volatile("cp.async.cg.shared.global [%0], [%1], 16;" :: "r"(dst), "l"(src) : "memory")
#define CP_COMMIT() asm volatile("cp.async.commit_group;" ::: "memory")
#define CP_WAIT(N)  asm volatile("cp.async.wait_group %0;" :: "n"(N) : "memory")

#define LDM4(r, a)                                                              \
    asm volatile("ldmatrix.sync.aligned.m8n8.x4.shared.b16 {%0,%1,%2,%3}, [%4];" \
                 : "=r"((r)[0]), "=r"((r)[1]), "=r"((r)[2]), "=r"((r)[3]) : "r"(a))

#define LDM4T(r, a)                                                                   \
    asm volatile("ldmatrix.sync.aligned.m8n8.x4.trans.shared.b16 {%0,%1,%2,%3}, [%4];" \
                 : "=r"((r)[0]), "=r"((r)[1]), "=r"((r)[2]), "=r"((r)[3]) : "r"(a))

#define MMA16816(c, a, b0, b1)                                                  \
    asm volatile("mma.sync.aligned.m16n8k16.row.col.f32.bf16.bf16.f32 "         \
                 "{%0,%1,%2,%3}, {%4,%5,%6,%7}, {%8,%9}, {%0,%1,%2,%3};"        \
                 : "+f"((c)[0]), "+f"((c)[1]), "+f"((c)[2]), "+f"((c)[3])       \
                 : "r"((a)[0]), "r"((a)[1]), "r"((a)[2]), "r"((a)[3]),          \
                   "r"(b0), "r"(b1))

// streaming zero-fill — write-once data, keep it out of L2
#define STG_CS_F4Z(addr) \
    asm volatile("st.global.cs.v4.f32 [%0], {%1, %1, %1, %1};" :: "l"(addr), "f"(0.f) : "memory")

__device__ __forceinline__ float ex2f(float x) {
    float r; asm("ex2.approx.f32 %0, %1;" : "=f"(r) : "f"(x)); return r;
}
__device__ __forceinline__ void split2(float x, float y, uint32_t& hi, uint32_t& lo) {
    __nv_bfloat16 hx = __float2bfloat16(x), hy = __float2bfloat16(y);
    __nv_bfloat162 hp(hx, hy);
    hi = *(uint32_t*)&hp;
    __nv_bfloat162 lp = __floats2bfloat162_rn(x - __bfloat162float(hx),
                                              y - __bfloat162float(hy));
    lo = *(uint32_t*)&lp;
}

// ---------------------------------------------------------------------------
// fp32 -> bf16 hi/lo split (x and weights only — everything else is fused)
// ---------------------------------------------------------------------------
__global__ __launch_bounds__(256) void conv_split(
    const float* __restrict__ src, __nv_bfloat16* __restrict__ hi,
    __nv_bfloat16* __restrict__ lo, int n)
{
    int i = (blockIdx.x * 256 + threadIdx.x) * 4;
    if (i >= n) return;
    float4 v = *(const float4*)&src[i];
    __nv_bfloat16 h0 = __float2bfloat16(v.x), h1 = __float2bfloat16(v.y);
    __nv_bfloat16 h2 = __float2bfloat16(v.z), h3 = __float2bfloat16(v.w);
    __nv_bfloat16 l0 = __float2bfloat16(v.x - __bfloat162float(h0));
    __nv_bfloat16 l1 = __float2bfloat16(v.y - __bfloat162float(h1));
    __nv_bfloat16 l2 = __float2bfloat16(v.z - __bfloat162float(h2));
    __nv_bfloat16 l3 = __float2bfloat16(v.w - __bfloat162float(h3));
    *(__nv_bfloat162*)&hi[i]     = __nv_bfloat162(h0, h1);
    *(__nv_bfloat162*)&hi[i + 2] = __nv_bfloat162(h2, h3);
    *(__nv_bfloat162*)&lo[i]     = __nv_bfloat162(l0, l1);
    *(__nv_bfloat162*)&lo[i + 2] = __nv_bfloat162(l2, l3);
}

// ---------------------------------------------------------------------------
// Tensor-core (mma.sync bf16) 3-split GEMM:
//   acc = Ah@Bh^T + Ah@Bl^T + Al@Bh^T + bias
// EMODE 0: write fp32 C.  EMODE 1: write bf16 hi/lo pair (fused conv_split).
// ---------------------------------------------------------------------------
#define GM_STEPS (HID / 32)
#define GM_TPAD  80
#define GM_TILE  (128 * GM_TPAD)
#define GM_BUF   (4 * GM_TILE)
#define GM_SMEM  (2 * GM_BUF)

template <int EMODE>
__global__ __launch_bounds__(256, 2) void gemm_mma(
    const __nv_bfloat16* __restrict__ Ah, const __nv_bfloat16* __restrict__ Al,
    const __nv_bfloat16* __restrict__ Bh, const __nv_bfloat16* __restrict__ Bl,
    const float* __restrict__ bias, float* __restrict__ Cf,
    __nv_bfloat16* __restrict__ Ch, __nv_bfloat16* __restrict__ Cl,
    int M, int N)
{
    extern __shared__ __align__(128) char sm[];
    const uint32_t smb = smem_u32(sm);
    const int tid = threadIdx.x;
    const int lane = tid & 31, w = tid >> 5;
    const int wr = w >> 2;
    const int wc = w & 3;
    const int m0 = blockIdx.y * 128, n0 = blockIdx.x * 128;
    const int K = HID;

    const __nv_bfloat16* gb[4] = {
        Ah + (size_t)m0 * K, Al + (size_t)m0 * K,
        Bh + (size_t)n0 * K, Bl + (size_t)n0 * K };

    auto load_step = [&](int b, int k0) {
        uint32_t bufb = smb + b * GM_BUF;
        #pragma unroll
        for (int j = 0; j < 8; j++) {
            int i = tid + j * 256;
            int t = i >> 9;
            int r = (i >> 2) & 127;
            int c = i & 3;
            const __nv_bfloat16* src = gb[t] + (size_t)r * K + k0 + c * 8;
            uint32_t dst = bufb + t * GM_TILE + r * GM_TPAD + c * 16;
            CP_ASYNC16(dst, src);
        }
    };

    float acc[4][4][4];
    #pragma unroll
    for (int mi = 0; mi < 4; mi++)
        #pragma unroll
        for (int nt = 0; nt < 4; nt++)
            #pragma unroll
            for (int r = 0; r < 4; r++) acc[mi][nt][r] = 0.f;

    const uint32_t a_off = (uint32_t)(wr * 64 + (lane & 15)) * GM_TPAD + (lane >> 4) * 16;
    const int q = lane >> 3;
    const uint32_t b_off = (uint32_t)(wc * 32 + (q >> 1) * 8 + (lane & 7)) * GM_TPAD
                         + (q & 1) * 16;

    load_step(0, 0);
    CP_COMMIT();

    for (int t = 0; t < GM_STEPS; t++) {
        if (t + 1 < GM_STEPS) {
            load_step((t + 1) & 1, (t + 1) * 32);
            CP_COMMIT();
            CP_WAIT(1);
        } else {
            CP_WAIT(0);
        }
        __syncthreads();

        const uint32_t bb = smb + (t & 1) * GM_BUF;
        #pragma unroll
        for (int kk = 0; kk < 2; kk++) {
            const uint32_t kb = kk * 32;
            uint32_t af[4][4], bh[4][2], bl[4][2];

            #pragma unroll
            for (int p = 0; p < 2; p++) {
                uint32_t rb = bb + 2 * GM_TILE + b_off + p * 16 * GM_TPAD + kb;
                uint32_t tmp[4];
                LDM4(tmp, rb);
                bh[2 * p][0] = tmp[0]; bh[2 * p][1] = tmp[1];
                bh[2 * p + 1][0] = tmp[2]; bh[2 * p + 1][1] = tmp[3];
                LDM4(tmp, rb + GM_TILE);
                bl[2 * p][0] = tmp[0]; bl[2 * p][1] = tmp[1];
                bl[2 * p + 1][0] = tmp[2]; bl[2 * p + 1][1] = tmp[3];
            }

            #pragma unroll
            for (int mi = 0; mi < 4; mi++) {
                LDM4(af[mi], bb + a_off + (uint32_t)mi * 16 * GM_TPAD + kb);
            }
            #pragma unroll
            for (int mi = 0; mi < 4; mi++)
                #pragma unroll
                for (int nt = 0; nt < 4; nt++) {
                    MMA16816(acc[mi][nt], af[mi], bh[nt][0], bh[nt][1]);
                    MMA16816(acc[mi][nt], af[mi], bl[nt][0], bl[nt][1]);
                }

            #pragma unroll
            for (int mi = 0; mi < 4; mi++) {
                LDM4(af[mi], bb + GM_TILE + a_off + (uint32_t)mi * 16 * GM_TPAD + kb);
            }
            #pragma unroll
            for (int mi = 0; mi < 4; mi++)
                #pragma unroll
                for (int nt = 0; nt < 4; nt++)
                    MMA16816(acc[mi][nt], af[mi], bh[nt][0], bh[nt][1]);
        }
        __syncthreads();
    }

    const int rbase = m0 + wr * 64 + (lane >> 2);
    #pragma unroll
    for (int nt = 0; nt < 4; nt++) {
        const int col = n0 + wc * 32 + nt * 8 + (lane & 3) * 2;
        const float2 bv = *(const float2*)&bias[col];
        #pragma unroll
        for (int mi = 0; mi < 4; mi++) {
            int r0 = rbase + mi * 16;
            float v00 = acc[mi][nt][0] + bv.x, v01 = acc[mi][nt][1] + bv.y;
            float v10 = acc[mi][nt][2] + bv.x, v11 = acc[mi][nt][3] + bv.y;
            if (EMODE == 0) {
                *(float2*)&Cf[(size_t)r0 * N + col]       = make_float2(v00, v01);
                *(float2*)&Cf[(size_t)(r0 + 8) * N + col] = make_float2(v10, v11);
            } else {
                uint32_t hi, lo;
                split2(v00, v01, hi, lo);
                *(uint32_t*)&Ch[(size_t)r0 * N + col] = hi;
                *(uint32_t*)&Cl[(size_t)r0 * N + col] = lo;
                split2(v10, v11, hi, lo);
                *(uint32_t*)&Ch[(size_t)(r0 + 8) * N + col] = hi;
                *(uint32_t*)&Cl[(size_t)(r0 + 8) * N + col] = lo;
            }
        }
    }
}

// ---------------------------------------------------------------------------
// Tensor-core causal flash attention (mma.sync, bf16 3-split).
// CTA: 256 threads = 8 warps; Q row tile 128 (warp = 16 rows); j-tile 64.
// 2 CTAs/SM; phase 2 processes nt in two halves to keep regs under 128
// without spills (sacc/aph live ranges halved).
// Phase 1: S = QK^T (3-term), online (m, l) stats only.
// Phase 2: recompute S (half-tile at a time), p = exp2(s*C - m)/l, write P,
//          ctx += P@V; ctx emitted as bf16 hi/lo for the O-projection.
// ---------------------------------------------------------------------------
#define AT_STRIDE 144
#define AT_QTILE  (128 * AT_STRIDE)
#define AT_Q      (2 * AT_QTILE)
#define AT_KVT    (64 * AT_STRIDE)
#define AT_KVBUF  (4 * AT_KVT)
#define AT_SMEM   (AT_Q + 2 * AT_KVBUF)
#define C_SCALE   11.5415603270f         // 8 * log2(e)

__global__ __launch_bounds__(256, 2) void attn_mma(
    const __nv_bfloat16* __restrict__ qh, const __nv_bfloat16* __restrict__ ql,
    const __nv_bfloat16* __restrict__ kh, const __nv_bfloat16* __restrict__ kl,
    const __nv_bfloat16* __restrict__ vh, const __nv_bfloat16* __restrict__ vl,
    float* __restrict__ attn,
    __nv_bfloat16* __restrict__ cth, __nv_bfloat16* __restrict__ ctl)
{
    extern __shared__ __align__(1024) char smc[];
    const uint32_t smb = smem_u32(smc);
    const int tid = threadIdx.x, lane = tid & 31, w = tid >> 5;
    const int mt = (int)gridDim.x - 1 - (int)blockIdx.x;   // heavy-first
    const int bh = blockIdx.y, b = bh >> 4, h = bh & 15;
    const int m0 = mt * 128;
    const int njt = 2 * mt + 2;
    const size_t hoff = (size_t)b * SEQ * HID + h * 64;
    const __nv_bfloat16* src[6] = { qh + hoff, ql + hoff, kh + hoff,
                                    kl + hoff, vh + hoff, vl + hoff };
    float* arow = attn + (size_t)bh * SEQ * SEQ;

    for (int i = tid; i < 2048; i += 256) {
        int t = i >> 10, r = (i >> 3) & 127, c = i & 7;
        CP_ASYNC16(smb + t * AT_QTILE + r * AT_STRIDE + c * 16,
                   src[t] + (size_t)(m0 + r) * HID + c * 8);
    }
    CP_COMMIT();

    auto load_kv = [&](int buf, int jt, int ntiles) {
        uint32_t base = smb + AT_Q + buf * AT_KVBUF;
        int j0 = jt * 64;
        for (int i = tid; i < ntiles * 512; i += 256) {
            int t = i >> 9, r = (i >> 3) & 63, c = i & 7;
            CP_ASYNC16(base + t * AT_KVT + r * AT_STRIDE + c * 16,
                       src[2 + t] + (size_t)(j0 + r) * HID + c * 8);
        }
    };

    const int wq = w * 16;
    const uint32_t qa  = smb + (uint32_t)(wq + (lane & 15)) * AT_STRIDE + (lane >> 4) * 16;
    const int q2 = lane >> 3;
    const uint32_t kfo = (uint32_t)((q2 >> 1) * 8 + (lane & 7)) * AT_STRIDE + (q2 & 1) * 16;
    const int rbase = m0 + wq + (lane >> 2);

    uint32_t qhf[4][4];
    bool qloaded = false;

    float m_[2] = { -1e30f, -1e30f };
    float l_[2] = { 0.f, 0.f };

    // ---------------- phase 1: stats ----------------
    load_kv(0, 0, 2);
    CP_COMMIT();
    for (int jt = 0; jt < njt; jt++) {
        if (jt + 1 < njt) { load_kv((jt + 1) & 1, jt + 1, 2); CP_COMMIT(); CP_WAIT(1); }
        else              { CP_WAIT(0); }
        __syncthreads();
        if (!qloaded) {
            qloaded = true;
            #pragma unroll
            for (int kt = 0; kt < 4; kt++) LDM4(qhf[kt], qa + kt * 32);
        }

        const uint32_t kb = smb + AT_Q + (jt & 1) * AT_KVBUF;
        float sacc[8][4];
        #pragma unroll
        for (int nt = 0; nt < 8; nt++)
            #pragma unroll
            for (int r = 0; r < 4; r++) sacc[nt][r] = 0.f;
        #pragma unroll
        for (int kt = 0; kt < 4; kt++) {
            uint32_t qlf[4];
            LDM4(qlf, qa + AT_QTILE + kt * 32);
            #pragma unroll
            for (int p = 0; p < 4; p++) {
                uint32_t kh4[4], kl4[4];
                uint32_t ka = kb + kfo + (uint32_t)p * 16 * AT_STRIDE + kt * 32;
                LDM4(kh4, ka);
                LDM4(kl4, ka + AT_KVT);
                MMA16816(sacc[2 * p],     qhf[kt], kh4[0], kh4[1]);
                MMA16816(sacc[2 * p + 1], qhf[kt], kh4[2], kh4[3]);
                MMA16816(sacc[2 * p],     qhf[kt], kl4[0], kl4[1]);
                MMA16816(sacc[2 * p + 1], qhf[kt], kl4[2], kl4[3]);
                MMA16816(sacc[2 * p],     qlf, kh4[0], kh4[1]);
                MMA16816(sacc[2 * p + 1], qlf, kh4[2], kh4[3]);
            }
        }

        const int colb = jt * 64 + (lane & 3) * 2;
        #pragma unroll
        for (int hf = 0; hf < 2; hf++) {
            const int row = rbase + 8 * hf;
            float sv[16];
            float tmax = -1e30f;
            #pragma unroll
            for (int nt = 0; nt < 8; nt++) {
                int c0 = colb + nt * 8;
                float s0 = (c0     > row) ? -1e30f : sacc[nt][2 * hf]     * C_SCALE;
                float s1 = (c0 + 1 > row) ? -1e30f : sacc[nt][2 * hf + 1] * C_SCALE;
                sv[2 * nt] = s0; sv[2 * nt + 1] = s1;
                tmax = fmaxf(tmax, fmaxf(s0, s1));
            }
            tmax = fmaxf(tmax, __shfl_xor_sync(0xffffffffu, tmax, 1));
            tmax = fmaxf(tmax, __shfl_xor_sync(0xffffffffu, tmax, 2));
            float mnew = fmaxf(m_[hf], tmax);
            float s = 0.f;
            #pragma unroll
            for (int e = 0; e < 16; e++) s += ex2f(sv[e] - mnew);
            s += __shfl_xor_sync(0xffffffffu, s, 1);
            s += __shfl_xor_sync(0xffffffffu, s, 2);
            l_[hf] = l_[hf] * ex2f(m_[hf] - mnew) + s;
            m_[hf] = mnew;
        }
        __syncthreads();
    }

    const float invl[2] = { 1.f / l_[0], 1.f / l_[1] };

    // ---------------- phase 2: P + PV (two n-halves, low reg pressure) ----
    float cacc[8][4];
    #pragma unroll
    for (int nt = 0; nt < 8; nt++)
        #pragma unroll
        for (int r = 0; r < 4; r++) cacc[nt][r] = 0.f;

    load_kv(0, 0, 4);
    CP_COMMIT();
    for (int jt = 0; jt < njt; jt++) {
        if (jt + 1 < njt) { load_kv((jt + 1) & 1, jt + 1, 4); CP_COMMIT(); CP_WAIT(1); }
        else              { CP_WAIT(0); }
        __syncthreads();

        const uint32_t kb = smb + AT_Q + (jt & 1) * AT_KVBUF;
        const uint32_t vb = kb + 2 * AT_KVT;
        const uint32_t vfo = vb + (uint32_t)(lane & 15) * AT_STRIDE + (lane >> 4) * 16;
        const int colb = jt * 64 + (lane & 3) * 2;

        #pragma unroll
        for (int half = 0; half < 2; half++) {
            // S for n-tiles [4*half, 4*half+3]
            float sacc[4][4];
            #pragma unroll
            for (int nt = 0; nt < 4; nt++)
                #pragma unroll
                for (int r = 0; r < 4; r++) sacc[nt][r] = 0.f;
            #pragma unroll
            for (int kt = 0; kt < 4; kt++) {
                uint32_t qlf[4];
                LDM4(qlf, qa + AT_QTILE + kt * 32);
                #pragma unroll
                for (int pl = 0; pl < 2; pl++) {
                    const int p = 2 * half + pl;
                    uint32_t kh4[4], kl4[4];
                    uint32_t ka = kb + kfo + (uint32_t)p * 16 * AT_STRIDE + kt * 32;
                    LDM4(kh4, ka);
                    LDM4(kl4, ka + AT_KVT);
                    MMA16816(sacc[2 * pl],     qhf[kt], kh4[0], kh4[1]);
                    MMA16816(sacc[2 * pl + 1], qhf[kt], kh4[2], kh4[3]);
                    MMA16816(sacc[2 * pl],     qhf[kt], kl4[0], kl4[1]);
                    MMA16816(sacc[2 * pl + 1], qhf[kt], kl4[2], kl4[3]);
                    MMA16816(sacc[2 * pl],     qlf, kh4[0], kh4[1]);
                    MMA16816(sacc[2 * pl + 1], qlf, kh4[2], kh4[3]);
                }
            }

            // exp, write P, pack A-fragments for PV
            uint32_t aph[2][4], apl[2][4];
            #pragma unroll
            for (int ntl = 0; ntl < 4; ntl++) {
                const int nt = 4 * half + ntl;
                int c0 = colb + nt * 8;
                int kjl = ntl >> 1, sub = ntl & 1;
                #pragma unroll
                for (int hf = 0; hf < 2; hf++) {
                    const int row = rbase + 8 * hf;
                    float p0 = (c0     > row) ? 0.f
                             : ex2f(fmaf(sacc[ntl][2 * hf],     C_SCALE, -m_[hf])) * invl[hf];
                    float p1 = (c0 + 1 > row) ? 0.f
                             : ex2f(fmaf(sacc[ntl][2 * hf + 1], C_SCALE, -m_[hf])) * invl[hf];
                    *(float2*)&arow[(size_t)row * SEQ + c0] = make_float2(p0, p1);
                    split2(p0, p1, aph[kjl][sub * 2 + hf], apl[kjl][sub * 2 + hf]);
                }
            }

            // PV for k-chunks [2*half, 2*half+1]
            #pragma unroll
            for (int kjl = 0; kjl < 2; kjl++) {
                const int kj = 2 * half + kjl;
                #pragma unroll
                for (int dp = 0; dp < 4; dp++) {
                    uint32_t vh4[4], vl4[4];
                    uint32_t va = vfo + (uint32_t)kj * 16 * AT_STRIDE + dp * 32;
                    LDM4T(vh4, va);
                    LDM4T(vl4, va + AT_KVT);
                    MMA16816(cacc[2 * dp],     aph[kjl], vh4[0], vh4[1]);
                    MMA16816(cacc[2 * dp + 1], aph[kjl], vh4[2], vh4[3]);
                    MMA16816(cacc[2 * dp],     aph[kjl], vl4[0], vl4[1]);
                    MMA16816(cacc[2 * dp + 1], aph[kjl], vl4[2], vl4[3]);
                    MMA16816(cacc[2 * dp],     apl[kjl], vh4[0], vh4[1]);
                    MMA16816(cacc[2 * dp + 1], apl[kjl], vh4[2], vh4[3]);
                }
            }
        }
        __syncthreads();
    }

    // ctx write — fused bf16 hi/lo split
    #pragma unroll
    for (int hf = 0; hf < 2; hf++) {
        const int row = rbase + 8 * hf;
        size_t off = ((size_t)b * SEQ + row) * HID + h * 64 + (lane & 3) * 2;
        #pragma unroll
        for (int nt = 0; nt < 8; nt++) {
            uint32_t hi, lo;
            split2(cacc[nt][2 * hf], cacc[nt][2 * hf + 1], hi, lo);
            *(uint32_t*)&cth[off + nt * 8] = hi;
            *(uint32_t*)&ctl[off + nt * 8] = lo;
        }
    }

    // zero-fill fully masked columns (streaming stores)
    const int zstart = m0 + 128;
    const int zc = SEQ - zstart;
    if (zc > 0) {
        const int nv = zc >> 2;
        for (int it = tid; it < 128 * nv; it += 256) {
            int r = it / nv, c = it - r * nv;
            STG_CS_F4Z(&arow[(size_t)(m0 + r) * SEQ + zstart + c * 4]);
        }
    }
}

// ---------------------------------------------------------------------------
extern "C" void kernel_launch(void* const* d_in, const int* in_sizes, int n_in,
                              void* d_out, int out_size)
{
    const float* x  = (const float*)d_in[0];
    const float* Wq = (const float*)d_in[1];
    const float* bq = (const float*)d_in[2];
    const float* Wk = (const float*)d_in[3];
    const float* bk = (const float*)d_in[4];
    const float* Wv = (const float*)d_in[5];
    const float* bv = (const float*)d_in[6];
    const float* Wo = (const float*)d_in[7];
    const float* bo = (const float*)d_in[8];

    float* out = (float*)d_out;

    void *pattn, *pah, *pal, *pwh, *pwl;
    void *pqh, *pql, *pkh, *pkl, *pvh, *pvl, *pcth, *pctl;
    cudaGetSymbolAddress(&pattn, g_attn_scratch);
    cudaGetSymbolAddress(&pah, g_ah);
    cudaGetSymbolAddress(&pal, g_al);
    cudaGetSymbolAddress(&pwh, g_wh);
    cudaGetSymbolAddress(&pwl, g_wl);
    cudaGetSymbolAddress(&pqh, g_qh);
    cudaGetSymbolAddress(&pql, g_ql);
    cudaGetSymbolAddress(&pkh, g_kh);
    cudaGetSymbolAddress(&pkl, g_kl);
    cudaGetSymbolAddress(&pvh, g_vh);
    cudaGetSymbolAddress(&pvl, g_vl);
    cudaGetSymbolAddress(&pcth, g_cth);
    cudaGetSymbolAddress(&pctl, g_ctl);

    __nv_bfloat16* ah = (__nv_bfloat16*)pah;
    __nv_bfloat16* al = (__nv_bfloat16*)pal;
    __nv_bfloat16* wh = (__nv_bfloat16*)pwh;
    __nv_bfloat16* wl = (__nv_bfloat16*)pwl;

    float* attn = ((size_t)out_size >= OUT_ELEMS + ATTN_ELEMS)
                      ? out + OUT_ELEMS
                      : (float*)pattn;

    cudaFuncSetAttribute(gemm_mma<0>, cudaFuncAttributeMaxDynamicSharedMemorySize, GM_SMEM);
    cudaFuncSetAttribute(gemm_mma<1>, cudaFuncAttributeMaxDynamicSharedMemorySize, GM_SMEM);
    cudaFuncSetAttribute(attn_mma, cudaFuncAttributeMaxDynamicSharedMemorySize, AT_SMEM);

    const int NW = HID * HID;    // 1,048,576
    const int NX = MROWS * HID;  // 4,194,304

    // input splits (x + 4 weights only)
    conv_split<<<NX / 1024, 256>>>(x, ah, al, NX);
    conv_split<<<NW / 1024, 256>>>(Wq, wh + 0 * (size_t)NW, wl + 0 * (size_t)NW, NW);
    conv_split<<<NW / 1024, 256>>>(Wk, wh + 1 * (size_t)NW, wl + 1 * (size_t)NW, NW);
    conv_split<<<NW / 1024, 256>>>(Wv, wh + 2 * (size_t)NW, wl + 2 * (size_t)NW, NW);
    conv_split<<<NW / 1024, 256>>>(Wo, wh + 3 * (size_t)NW, wl + 3 * (size_t)NW, NW);

    dim3 gG(HID / 128, MROWS / 128);  // (8, 32)
    // Q/K/V projections: bf16 hi/lo emitted directly (EMODE 1)
    gemm_mma<1><<<gG, 256, GM_SMEM>>>(ah, al, wh + 0 * (size_t)NW, wl + 0 * (size_t)NW,
                                      bq, nullptr,
                                      (__nv_bfloat16*)pqh, (__nv_bfloat16*)pql, MROWS, HID);
    gemm_mma<1><<<gG, 256, GM_SMEM>>>(ah, al, wh + 1 * (size_t)NW, wl + 1 * (size_t)NW,
                                      bk, nullptr,
                                      (__nv_bfloat16*)pkh, (__nv_bfloat16*)pkl, MROWS, HID);
    gemm_mma<1><<<gG, 256, GM_SMEM>>>(ah, al, wh + 2 * (size_t)NW, wl + 2 * (size_t)NW,
                                      bv, nullptr,
                                      (__nv_bfloat16*)pvh, (__nv_bfloat16*)pvl, MROWS, HID);

    dim3 gAttn(SEQ / 128, BATCH * NH);  // (16, 32)
    attn_mma<<<gAttn, 256, AT_SMEM>>>(
        (const __nv_bfloat16*)pqh, (const __nv_bfloat16*)pql,
        (const __nv_bfloat16*)pkh, (const __nv_bfloat16*)pkl,
        (const __nv_bfloat16*)pvh, (const __nv_bfloat16*)pvl,
        attn, (__nv_bfloat16*)pcth, (__nv_bfloat16*)pctl);

    // O projection consumes fused ctx hi/lo, writes fp32 out (EMODE 0)
    gemm_mma<0><<<gG, 256, GM_SMEM>>>((const __nv_bfloat16*)pcth, (const __nv_bfloat16*)pctl,
                                      wh + 3 * (size_t)NW, wl + 3 * (size_t)NW,
                                      bo, out, nullptr, nullptr, MROWS, HID);
}